// round 16
// baseline (speedup 1.0000x reference)
#include <cuda_runtime.h>
#include <cuda_bf16.h>
#include <mma.h>
#include <math.h>
#include <stdint.h>

#define BB 64
#define CC 5
#define HH 50
#define LL 32
#define DD 300
#define QQ 200
#define VV 50000
#define NSLOT 55
#define MNEWS 2048           // BB*LL
#define MUSER 3200           // BB*HH
#define MTOT (NSLOT*MNEWS)   // 112640
#define SCAP 3200
#define NSL2 (NSLOT + 1)
#define JC 256
#define MAXCH 13
#define CPAD 304

// wmma GEMM geometry: block tile 128x64, K-tile 32, double-buffered
#define NT 10
#define ALD 40                      // A smem ld (bf16), 128x32+pad
#define BLD 72                      // B smem ld (bf16), 32x64+pad
#define CLD 72                      // C smem ld (f32)
#define ASTGE (128 * ALD)           // 5120 bf16 per A half
#define BSTGE (32 * BLD)            // 2304 bf16 per B half
#define STGE (2 * ASTGE + 2 * BSTGE) // 14848 bf16 per stage
#define DSMB (2 * STGE * 2)         // 59392 B (C dump needs 128*72*4=36864 <= this)

using namespace nvcuda;
typedef __nv_bfloat16 bf16;

__device__ __forceinline__ void split2(float x, bf16& h, bf16& l) {
    h = __float2bfloat16(x);
    l = __float2bfloat16(x - __bfloat162float(h));
}

// ---------------- static scratch ----------------
__device__ float d_embW[(size_t)VV * DD];
__device__ float d_vs[VV];
__device__ float d_vt[VV];
__device__ float d_V[(size_t)MTOT * DD];
__device__ float d_Wh[(size_t)MTOT * DD];
__device__ float d_sv[MTOT];
__device__ float d_tv[MTOT];
__device__ float d_enc[(size_t)NSLOT * BB * DD];
__device__ float d_uV[(size_t)MUSER * DD];
__device__ float d_uWh[(size_t)MUSER * DD];
__device__ float d_us[MUSER];
__device__ float d_ut[MUSER];
__device__ float d_uG[(size_t)MUSER * DD];
__device__ float d_user[(size_t)BB * DD];

__device__ float g_ts [(size_t)NSL2 * SCAP];
__device__ float g_E1 [(size_t)NSL2 * SCAP];
__device__ float g_E2 [(size_t)NSL2 * SCAP];
__device__ int   g_ti [(size_t)NSL2 * SCAP];
__device__ float g_thr[(size_t)NSL2 * SCAP];
__device__ float g_es1[(size_t)NSL2 * SCAP];
__device__ float g_es2[(size_t)NSL2 * SCAP];
__device__ int   g_si [(size_t)NSL2 * SCAP];

__device__ float g_cp1[(size_t)NSL2 * MAXCH * CPAD];
__device__ float g_cp2[(size_t)NSL2 * MAXCH * CPAD];
__device__ float g_cc1[NSL2 * MAXCH];
__device__ float g_cc2[NSL2 * MAXCH];

__device__ float g_score[MTOT];
__device__ float g_uscore[MUSER];
__device__ float g_lwTn[DD * QQ];
__device__ float g_lwTu[DD * QQ];

// ---------------- prep ----------------
__global__ void prep_kernel(const float* __restrict__ lwN, const float* __restrict__ lwU) {
    int i = blockIdx.x * 256 + threadIdx.x;
    if (i < MTOT) g_score[i] = 0.f;
    if (i < MUSER) { g_uscore[i] = 0.f; d_us[i] = 0.f; d_ut[i] = 0.f; }
    if (i < VV) { d_vs[i] = 0.f; d_vt[i] = 0.f; }
    if (i < DD * QQ) {
        int d = i / QQ, q = i - d * QQ;
        g_lwTn[i] = lwN[q * DD + d];
        g_lwTu[i] = lwU[q * DD + d];
    }
}

// ---------------- gather Wh rows (+ per-row s,t) ----------------
__global__ void gatherWh_kernel(const int* __restrict__ cand,
                                const int* __restrict__ clicked) {
    int row  = blockIdx.x * 8 + (threadIdx.x >> 5);
    int lane = threadIdx.x & 31;
    if (row >= MTOT) return;
    int slot = row / MNEWS;
    int r    = row - slot * MNEWS;
    int b = r >> 5, l = r & 31;
    int tok = (slot < CC) ? cand[(b * CC + slot) * LL + l]
                          : clicked[(b * HH + (slot - CC)) * LL + l];
    tok = min(max(tok, 0), VV - 1);
    const float2* src = (const float2*)(d_embW + (size_t)tok * DD);
    float2* dst = (float2*)(d_Wh + (size_t)row * DD);
    for (int c = lane; c < DD / 2; c += 32) dst[c] = src[c];
    if (!lane) { d_sv[row] = d_vs[tok]; d_tv[row] = d_vt[tok]; }
}

// ---------------- wmma split-bf16 GEMM core: 128x64 tile, double-buffered ------
__device__ __forceinline__ void wgemm_compute(const float* __restrict__ A,
                                              const float* __restrict__ Bm,
                                              int NW, int M, int mBase, int nBase,
                                              char* smc) {
    int tid = threadIdx.x;
    int wid = tid >> 5;
    int wm = wid & 3;          // rows wm*32
    int wn = wid >> 2;         // cols wn*32 (0..1)

    wmma::fragment<wmma::accumulator, 16, 16, 16, float> acc[2][2];
#pragma unroll
    for (int m = 0; m < 2; m++)
#pragma unroll
        for (int n = 0; n < 2; n++) wmma::fill_fragment(acc[m][n], 0.f);

    int arow = tid >> 3, acol = tid & 7;       // A: row, float4-idx in k
    int brow = tid >> 3, bcol = (tid & 7) * 8; // B: k-row, col base (8 floats/thread)
    bool aok[4];
#pragma unroll
    for (int rr = 0; rr < 4; rr++) aok[rr] = (mBase + arow + 32 * rr) < M;
    bool bok[2];
#pragma unroll
    for (int q = 0; q < 2; q++) bok[q] = (nBase + bcol + q * 4 + 3) < NW;

    float4 va[4], vb[2];

    auto ldg = [&](int kt) {
#pragma unroll
        for (int rr = 0; rr < 4; rr++) {
            float4 v = make_float4(0.f, 0.f, 0.f, 0.f);
            if (aok[rr] && (kt + acol * 4 + 3) < DD)
                v = *(const float4*)&A[(size_t)(mBase + arow + 32 * rr) * DD + kt + acol * 4];
            va[rr] = v;
        }
        bool rok = (kt + brow) < DD;
#pragma unroll
        for (int q = 0; q < 2; q++) {
            float4 v = make_float4(0.f, 0.f, 0.f, 0.f);
            if (rok && bok[q])
                v = *(const float4*)&Bm[(size_t)(kt + brow) * NW + nBase + bcol + q * 4];
            vb[q] = v;
        }
    };
    auto sts = [&](int buf) {
        bf16* Ahi = (bf16*)smc + buf * STGE;
        bf16* Alo = Ahi + ASTGE;
        bf16* Bhi = Alo + ASTGE;
        bf16* Blo = Bhi + BSTGE;
#pragma unroll
        for (int rr = 0; rr < 4; rr++) {
            bf16 h0, h1, h2, h3, l0, l1, l2, l3;
            split2(va[rr].x, h0, l0); split2(va[rr].y, h1, l1);
            split2(va[rr].z, h2, l2); split2(va[rr].w, h3, l3);
            __nv_bfloat162* ph = (__nv_bfloat162*)&Ahi[(arow + 32 * rr) * ALD + acol * 4];
            __nv_bfloat162* pl = (__nv_bfloat162*)&Alo[(arow + 32 * rr) * ALD + acol * 4];
            ph[0] = __halves2bfloat162(h0, h1); ph[1] = __halves2bfloat162(h2, h3);
            pl[0] = __halves2bfloat162(l0, l1); pl[1] = __halves2bfloat162(l2, l3);
        }
#pragma unroll
        for (int q = 0; q < 2; q++) {
            bf16 h0, h1, h2, h3, l0, l1, l2, l3;
            split2(vb[q].x, h0, l0); split2(vb[q].y, h1, l1);
            split2(vb[q].z, h2, l2); split2(vb[q].w, h3, l3);
            __nv_bfloat162* ph = (__nv_bfloat162*)&Bhi[brow * BLD + bcol + q * 4];
            __nv_bfloat162* pl = (__nv_bfloat162*)&Blo[brow * BLD + bcol + q * 4];
            ph[0] = __halves2bfloat162(h0, h1); ph[1] = __halves2bfloat162(h2, h3);
            pl[0] = __halves2bfloat162(l0, l1); pl[1] = __halves2bfloat162(l2, l3);
        }
    };
    auto mma = [&](int buf) {
        bf16* Ahi = (bf16*)smc + buf * STGE;
        bf16* Alo = Ahi + ASTGE;
        bf16* Bhi = Alo + ASTGE;
        bf16* Blo = Bhi + BSTGE;
#pragma unroll
        for (int kk = 0; kk < 32; kk += 16) {
            wmma::fragment<wmma::matrix_a, 16, 16, 16, bf16, wmma::row_major> ah[2], al[2];
#pragma unroll
            for (int m = 0; m < 2; m++) {
                wmma::load_matrix_sync(ah[m], Ahi + (wm * 32 + m * 16) * ALD + kk, ALD);
                wmma::load_matrix_sync(al[m], Alo + (wm * 32 + m * 16) * ALD + kk, ALD);
            }
#pragma unroll
            for (int n = 0; n < 2; n++) {
                wmma::fragment<wmma::matrix_b, 16, 16, 16, bf16, wmma::row_major> bh, bl;
                wmma::load_matrix_sync(bh, Bhi + kk * BLD + wn * 32 + n * 16, BLD);
                wmma::load_matrix_sync(bl, Blo + kk * BLD + wn * 32 + n * 16, BLD);
#pragma unroll
                for (int m = 0; m < 2; m++) {
                    wmma::mma_sync(acc[m][n], ah[m], bh, acc[m][n]);
                    wmma::mma_sync(acc[m][n], ah[m], bl, acc[m][n]);
                    wmma::mma_sync(acc[m][n], al[m], bh, acc[m][n]);
                }
            }
        }
    };

    ldg(0); sts(0);
#pragma unroll 1
    for (int it = 0; it < NT; it++) {
        __syncthreads();
        bool more = (it + 1) < NT;
        if (more) ldg((it + 1) * 32);
        mma(it & 1);
        if (more) sts((it + 1) & 1);
    }
    __syncthreads();

    float* Cs = (float*)smc;
#pragma unroll
    for (int m = 0; m < 2; m++)
#pragma unroll
        for (int n = 0; n < 2; n++)
            wmma::store_matrix_sync(Cs + (wm * 32 + m * 16) * CLD + wn * 32 + n * 16,
                                    acc[m][n], CLD, wmma::mem_row_major);
    __syncthreads();
}

// ---------------- SGEMM: C[M,300] = A[M,300] @ B[300,300] + fused s,t ----------
__global__ void __launch_bounds__(256, 2)
gemm_kernel(const float* __restrict__ A, const float* __restrict__ Bm,
            float* __restrict__ Cm, int M,
            const float* __restrict__ a2, float* __restrict__ sv, float* __restrict__ tv) {
    extern __shared__ __align__(16) char smc[];
    int nBase = blockIdx.x * 64;
    int mBase = blockIdx.y * 128;
    int tid = threadIdx.x;
    int ti = tid >> 4, td = tid & 15;

    wgemm_compute(A, Bm, DD, M, mBase, nBase, smc);
    const float* Cs = (const float*)smc;

    int col0 = nBase + td * 4;
#pragma unroll
    for (int r = 0; r < 8; r++) {
        int mrow = mBase + ti * 8 + r;
        if (mrow >= M) continue;
        float* crow = Cm + (size_t)mrow * DD;
        float o[4];
#pragma unroll
        for (int e = 0; e < 4; e++) o[e] = Cs[(ti * 8 + r) * CLD + td * 4 + e];
        if (col0 + 3 < DD) {
            *(float4*)&crow[col0] = make_float4(o[0], o[1], o[2], o[3]);
        } else {
#pragma unroll
            for (int e = 0; e < 4; e++)
                if (col0 + e < DD) crow[col0 + e] = o[e];
        }
        float sp = 0.f, tp = 0.f;
#pragma unroll
        for (int e = 0; e < 4; e++) {
            int col = col0 + e;
            if (col < DD) {
                sp += o[e] * a2[col];
                tp += o[e] * a2[DD + col];
            }
        }
        atomicAdd(&sv[mrow], sp);
        atomicAdd(&tv[mrow], tp);
    }
}

// ---------------- score GEMM ----------------
__global__ void __launch_bounds__(256, 2)
score_gemm_kernel(const float* __restrict__ A, const float* __restrict__ Bt,
                  const float* __restrict__ lin_b, const float* __restrict__ query,
                  float* __restrict__ score) {
    extern __shared__ __align__(16) char smc[];
    __shared__ float ssum[128];
    int nBase = blockIdx.x * 64;
    int mBase = blockIdx.y * 128;
    int tid = threadIdx.x;
    int ti = tid >> 4, td = tid & 15;

    wgemm_compute(A, Bt, QQ, 0x7fffffff, mBase, nBase, smc);
    const float* Cs = (const float*)smc;

    if (tid < 128) ssum[tid] = 0.f;
    __syncthreads();

    int col0 = nBase + td * 4;
#pragma unroll
    for (int r = 0; r < 8; r++) {
        float rs = 0.f;
#pragma unroll
        for (int e = 0; e < 4; e++) {
            int col = col0 + e;
            if (col < QQ) {
                float o = Cs[(ti * 8 + r) * CLD + td * 4 + e];
                rs += tanhf(o + lin_b[col]) * query[col];
            }
        }
        atomicAdd(&ssum[ti * 8 + r], rs);
    }
    __syncthreads();
    if (tid < 128) atomicAdd(&score[mBase + tid], ssum[tid]);
}

// ---------------- bitonic sort (two independent phases via blockIdx.y) ---------
template<int NS>
__device__ void bitonicNS(float* key, int* val) {
    for (int k = 2; k <= NS; k <<= 1) {
        for (int j = k >> 1; j > 0; j >>= 1) {
            for (int t = threadIdx.x; t < NS / 2; t += blockDim.x) {
                int i = 2 * t - (t & (j - 1));
                int l = i + j;
                bool up = ((i & k) == 0);
                float ki = key[i], kl = key[l];
                if (up ? (ki > kl) : (ki < kl)) {
                    key[i] = kl; key[l] = ki;
                    int vi = val[i]; val[i] = val[l]; val[l] = vi;
                }
            }
            __syncthreads();
        }
    }
}

template<int NS>
__global__ void __launch_bounds__(1024)
sort_kernel(const float* __restrict__ tv, const float* __restrict__ sv,
            int M, int slotBase) {
    __shared__ float key[NS];
    __shared__ int   val[NS];
    int slot = slotBase + blockIdx.x;
    size_t sb = (size_t)slot * SCAP;

    if (blockIdx.y == 0) {
        const float* t = tv + (size_t)blockIdx.x * M;
        for (int i = threadIdx.x; i < NS; i += blockDim.x) {
            key[i] = (i < M) ? t[i] : 3.0e38f;
            val[i] = i;
        }
        __syncthreads();
        bitonicNS<NS>(key, val);
        for (int i = threadIdx.x; i < M; i += blockDim.x) {
            float k = key[i];
            g_ts[sb + i] = k;
            g_ti[sb + i] = val[i];
            g_E1[sb + i] = __expf(k);
            g_E2[sb + i] = __expf(0.2f * k);
        }
    } else {
        const float* s = sv + (size_t)blockIdx.x * M;
        for (int i = threadIdx.x; i < NS; i += blockDim.x) {
            key[i] = (i < M) ? (-s[i]) : 3.0e38f;
            val[i] = i;
        }
        __syncthreads();
        bitonicNS<NS>(key, val);
        for (int i = threadIdx.x; i < M; i += blockDim.x) {
            float k = key[i];
            g_thr[sb + i] = k;
            g_si [sb + i] = val[i];
            g_es1[sb + i] = __expf(-k);
            g_es2[sb + i] = __expf(-0.2f * k);
        }
    }
}

// ---------------- phase A: per-chunk partial sums ----------------
__global__ void __launch_bounds__(320)
partials_kernel(const float* __restrict__ Wbase, size_t wStride, int M, int slotBase) {
    int slot = slotBase + blockIdx.y;
    size_t sb = (size_t)slot * SCAP;
    const float* W = Wbase + (size_t)blockIdx.y * wStride;
    int ch = blockIdx.x;
    int jstart = ch * JC, jend = min(M, jstart + JC);
    int t = threadIdx.x;

    if (t < DD) {
        int d = t;
        float p1 = 0.f, p2 = 0.f;
        float wb[4];
#pragma unroll
        for (int q = 0; q < 4; q++) wb[q] = W[(size_t)g_ti[sb + jstart + q] * DD + d];
        for (int jb = jstart; jb < jend; jb += 4) {
            float wn[4] = {0.f, 0.f, 0.f, 0.f};
            if (jb + 4 < jend) {
#pragma unroll
                for (int q = 0; q < 4; q++)
                    wn[q] = W[(size_t)g_ti[sb + jb + 4 + q] * DD + d];
            }
#pragma unroll
            for (int q = 0; q < 4; q++) {
                float e1 = g_E1[sb + jb + q], e2 = g_E2[sb + jb + q];
                p1 += e1 * wb[q]; p2 += e2 * wb[q];
            }
#pragma unroll
            for (int q = 0; q < 4; q++) wb[q] = wn[q];
        }
        size_t o = (size_t)(slot * MAXCH + ch) * CPAD + d;
        g_cp1[o] = p1; g_cp2[o] = p2;
    } else if (t == DD) {
        float c = 0.f;
        for (int j = jstart; j < jend; j++) c += g_E1[sb + j];
        g_cc1[slot * MAXCH + ch] = c;
    } else if (t == DD + 1) {
        float c = 0.f;
        for (int j = jstart; j < jend; j++) c += g_E2[sb + j];
        g_cc2[slot * MAXCH + ch] = c;
    }
}

// ---------------- phase C: per-chunk merge sweep ----------------
__global__ void __launch_bounds__(320)
csweep_kernel(const float* __restrict__ Wbase, size_t wStride, float* __restrict__ G_all,
              int M, int slotBase, int nch) {
    __shared__ float ts[JC], e1s[JC], e2s[JC];
    __shared__ int tis[JC];
    int slot = slotBase + blockIdx.y;
    size_t sb = (size_t)slot * SCAP;
    const float* W = Wbase + (size_t)blockIdx.y * wStride;
    float* G = G_all + (size_t)blockIdx.y * M * DD;
    int ch = blockIdx.x;
    int jstart = ch * JC, jend = min(M, jstart + JC);
    int jn = jend - jstart;

    for (int i = threadIdx.x; i < jn; i += blockDim.x) {
        ts[i]  = g_ts[sb + jstart + i];
        e1s[i] = g_E1[sb + jstart + i];
        e2s[i] = g_E2[sb + jstart + i];
        tis[i] = g_ti[sb + jstart + i];
    }
    __syncthreads();

    int t = threadIdx.x;
    bool act = t < DD;
    int d = act ? t : DD - 1;

    float p1 = 0.f, p2 = 0.f, c1 = 0.f, c2 = 0.f, T1 = 0.f, C1 = 0.f;
    int base = slot * MAXCH;
    for (int k = 0; k < nch; k++) {
        float v1 = g_cp1[(size_t)(base + k) * CPAD + d];
        float s1 = g_cc1[base + k];
        T1 += v1; C1 += s1;
        if (k < ch) {
            p1 += v1; c1 += s1;
            p2 += g_cp2[(size_t)(base + k) * CPAD + d];
            c2 += g_cc2[base + k];
        }
    }

    float tPrev = (jstart == 0) ? -3.4e38f : g_ts[sb + jstart - 1];
    int lo = 0, hi = M;
    while (lo < hi) { int mid = (lo + hi) >> 1; if (g_thr[sb + mid] <= tPrev) lo = mid + 1; else hi = mid; }
    int ptr = lo;
    int r1 = M;
    if (jend < M) {
        float tLast = ts[jn - 1];
        lo = 0; hi = M;
        while (lo < hi) { int mid = (lo + hi) >> 1; if (g_thr[sb + mid] <= tLast) lo = mid + 1; else hi = mid; }
        r1 = lo;
    }

    float wb[4];
#pragma unroll
    for (int q = 0; q < 4; q++) wb[q] = W[(size_t)tis[q] * DD + d];

    for (int jb = 0; jb < jn; jb += 4) {
        float wn[4] = {0.f, 0.f, 0.f, 0.f};
        if (jb + 4 < jn) {
#pragma unroll
            for (int q = 0; q < 4; q++) wn[q] = W[(size_t)tis[jb + 4 + q] * DD + d];
        }
#pragma unroll
        for (int q = 0; q < 4; q++) {
            float tj = ts[jb + q];
            while (ptr < r1 && g_thr[sb + ptr] <= tj) {
                float a1 = g_es1[sb + ptr], a2 = g_es2[sb + ptr];
                int si = g_si[sb + ptr];
                float den = a1 * (C1 - c1) + a2 * c2;
                float v = __fdividef(a1 * (T1 - p1) + a2 * p2, den);
                v = (v > 0.f) ? v : (__expf(v) - 1.f);
                if (act) G[(size_t)si * DD + d] = v;
                ptr++;
            }
            float e1 = e1s[jb + q], e2 = e2s[jb + q];
            p1 += e1 * wb[q]; p2 += e2 * wb[q];
            c1 += e1; c2 += e2;
        }
#pragma unroll
        for (int q = 0; q < 4; q++) wb[q] = wn[q];
    }
    while (ptr < r1) {
        float a1 = g_es1[sb + ptr], a2 = g_es2[sb + ptr];
        int si = g_si[sb + ptr];
        float den = a1 * (C1 - c1) + a2 * c2;
        float v = __fdividef(a1 * (T1 - p1) + a2 * p2, den);
        v = (v > 0.f) ? v : (__expf(v) - 1.f);
        if (act) G[(size_t)si * DD + d] = v;
        ptr++;
    }
}

// ---------------- softmax + weighted sum ----------------
__global__ void softsum_kernel(const float* __restrict__ X, const float* __restrict__ sc,
                               int S, int slotM, float* __restrict__ outB) {
    __shared__ float wsm[64];
    int b = blockIdx.x, slot = blockIdx.y;
    int rowBase = slot * slotM + b * S;
    int lane = threadIdx.x;
    if (threadIdx.x < 32) {
        float v0 = (lane < S) ? sc[rowBase + lane] : -1e30f;
        float v1 = ((lane + 32) < S) ? sc[rowBase + lane + 32] : -1e30f;
        float m = fmaxf(v0, v1);
#pragma unroll
        for (int o = 16; o; o >>= 1) m = fmaxf(m, __shfl_xor_sync(0xffffffffu, m, o));
        float e0 = (lane < S) ? __expf(v0 - m) : 0.f;
        float e1 = ((lane + 32) < S) ? __expf(v1 - m) : 0.f;
        float sum = e0 + e1;
#pragma unroll
        for (int o = 16; o; o >>= 1) sum += __shfl_xor_sync(0xffffffffu, sum, o);
        float inv = 1.f / sum;
        wsm[lane] = e0 * inv;
        wsm[lane + 32] = e1 * inv;
    }
    __syncthreads();
    float* o = outB + (size_t)(slot * BB + b) * DD;
    for (int dd = threadIdx.x; dd < DD; dd += blockDim.x) {
        float acc = 0.f;
        for (int s = 0; s < S; s++)
            acc += wsm[s] * X[(size_t)(rowBase + s) * DD + dd];
        o[dd] = acc;
    }
}

// ---------------- reorder clicked encodings ----------------
__global__ void copy_uV_kernel() {
    int row  = blockIdx.x * 8 + (threadIdx.x >> 5);
    int lane = threadIdx.x & 31;
    if (row >= MUSER) return;
    int b = row / HH, j = row - b * HH;
    const float* src = d_enc + ((size_t)(CC + j) * BB + b) * DD;
    float* dst = d_uV + (size_t)row * DD;
    for (int c = lane; c < DD; c += 32) dst[c] = src[c];
}

// ---------------- final scores ----------------
__global__ void scores_kernel(float* __restrict__ out) {
    int w    = (blockIdx.x * blockDim.x + threadIdx.x) >> 5;
    int lane = threadIdx.x & 31;
    if (w >= BB * CC) return;
    int b = w / CC, c = w - b * CC;
    const float* cd = d_enc + ((size_t)c * BB + b) * DD;
    const float* u  = d_user + (size_t)b * DD;
    float acc = 0.f;
    for (int k = lane; k < DD; k += 32) acc += cd[k] * u[k];
#pragma unroll
    for (int o = 16; o; o >>= 1) acc += __shfl_xor_sync(0xffffffffu, acc, o);
    if (!lane) out[b * CC + c] = acc;
}

// ---------------- launch ----------------
extern "C" void kernel_launch(void* const* d_in, const int* in_sizes, int n_in,
                              void* d_out, int out_size) {
    const void* by200[4] = {0, 0, 0, 0};
    const void* by600[2] = {0, 0};
    const void* by60k[2] = {0, 0};
    const void* by90k[2] = {0, 0};
    const int* cand = 0; const int* clicked = 0; const float* emb = 0;
    int n200 = 0, n600 = 0, n60k = 0, n90k = 0;
    for (int i = 0; i < n_in; i++) {
        int sz = in_sizes[i];
        if      (sz == BB * CC * LL)      cand    = (const int*)d_in[i];
        else if (sz == BB * HH * LL)      clicked = (const int*)d_in[i];
        else if (sz == VV * DD)           emb     = (const float*)d_in[i];
        else if (sz == DD * DD  && n90k < 2) by90k[n90k++] = d_in[i];
        else if (sz == 2 * DD   && n600 < 2) by600[n600++] = d_in[i];
        else if (sz == QQ * DD  && n60k < 2) by60k[n60k++] = d_in[i];
        else if (sz == QQ       && n200 < 4) by200[n200++] = d_in[i];
    }
    const float* news_W     = (const float*)by90k[0];
    const float* user_W     = (const float*)by90k[1];
    const float* news_a     = (const float*)by600[0];
    const float* user_a     = (const float*)by600[1];
    const float* news_lin_w = (const float*)by60k[0];
    const float* user_lin_w = (const float*)by60k[1];
    const float* news_lin_b = (const float*)by200[0];
    const float* news_query = (const float*)by200[1];
    const float* user_lin_b = (const float*)by200[2];
    const float* user_query = (const float*)by200[3];
    float* out = (float*)d_out;

    float *pEmbW, *pVs, *pVt, *pV, *pWh, *pS, *pT, *pEnc;
    float *pUV, *pUWh, *pUS, *pUT, *pUG, *pUser;
    float *pScore, *pUScore, *pLwTn, *pLwTu;
    cudaGetSymbolAddress((void**)&pEmbW, d_embW);
    cudaGetSymbolAddress((void**)&pVs, d_vs);
    cudaGetSymbolAddress((void**)&pVt, d_vt);
    cudaGetSymbolAddress((void**)&pV, d_V);
    cudaGetSymbolAddress((void**)&pWh, d_Wh);
    cudaGetSymbolAddress((void**)&pS, d_sv);
    cudaGetSymbolAddress((void**)&pT, d_tv);
    cudaGetSymbolAddress((void**)&pEnc, d_enc);
    cudaGetSymbolAddress((void**)&pUV, d_uV);
    cudaGetSymbolAddress((void**)&pUWh, d_uWh);
    cudaGetSymbolAddress((void**)&pUS, d_us);
    cudaGetSymbolAddress((void**)&pUT, d_ut);
    cudaGetSymbolAddress((void**)&pUG, d_uG);
    cudaGetSymbolAddress((void**)&pUser, d_user);
    cudaGetSymbolAddress((void**)&pScore, g_score);
    cudaGetSymbolAddress((void**)&pUScore, g_uscore);
    cudaGetSymbolAddress((void**)&pLwTn, g_lwTn);
    cudaGetSymbolAddress((void**)&pLwTu, g_lwTu);

    const int NCH_NEWS = (MNEWS + JC - 1) / JC;   // 8
    const int NCH_USER = (MUSER + JC - 1) / JC;   // 13

    cudaFuncSetAttribute(gemm_kernel, cudaFuncAttributeMaxDynamicSharedMemorySize, DSMB);
    cudaFuncSetAttribute(score_gemm_kernel, cudaFuncAttributeMaxDynamicSharedMemorySize, DSMB);

    // prep (zeros + both lin_w transposes)
    prep_kernel<<<(MTOT + 255) / 256, 256>>>(news_lin_w, user_lin_w);

    // news pipeline: vocab GEMM (+fused s,t) then per-slot contiguous gather
    gemm_kernel<<<dim3(5, (VV + 127) / 128), 256, DSMB>>>(emb, news_W, pEmbW, VV,
                                                          news_a, pVs, pVt);
    gatherWh_kernel<<<MTOT / 8, 256>>>(cand, clicked);
    sort_kernel<2048><<<dim3(NSLOT, 2), 1024>>>(pT, pS, MNEWS, 0);
    partials_kernel<<<dim3(NCH_NEWS, NSLOT), 320>>>(pWh, (size_t)MNEWS * DD, MNEWS, 0);
    csweep_kernel<<<dim3(NCH_NEWS, NSLOT), 320>>>(pWh, (size_t)MNEWS * DD, pV, MNEWS, 0, NCH_NEWS);
    score_gemm_kernel<<<dim3(4, MTOT / 128), 256, DSMB>>>(pV, pLwTn, news_lin_b, news_query, pScore);
    softsum_kernel<<<dim3(BB, NSLOT), 128>>>(pV, pScore, LL, MNEWS, pEnc);

    // user pipeline
    copy_uV_kernel<<<MUSER / 8, 256>>>();
    gemm_kernel<<<dim3(5, MUSER / 128), 256, DSMB>>>(pUV, user_W, pUWh, MUSER,
                                                     user_a, pUS, pUT);
    sort_kernel<4096><<<dim3(1, 2), 1024>>>(pUT, pUS, MUSER, NSLOT);
    partials_kernel<<<dim3(NCH_USER, 1), 320>>>(pUWh, 0, MUSER, NSLOT);
    csweep_kernel<<<dim3(NCH_USER, 1), 320>>>(pUWh, 0, pUG, MUSER, NSLOT, NCH_USER);
    score_gemm_kernel<<<dim3(4, MUSER / 128), 256, DSMB>>>(pUG, pLwTu, user_lin_b, user_query, pUScore);
    softsum_kernel<<<dim3(BB, 1), 128>>>(pUG, pUScore, HH, MUSER, pUser);

    scores_kernel<<<40, 256>>>(out);
}

// round 17
// speedup vs baseline: 1.1414x; 1.1414x over previous
#include <cuda_runtime.h>
#include <cuda_bf16.h>
#include <mma.h>
#include <math.h>
#include <stdint.h>

#define BB 64
#define CC 5
#define HH 50
#define LL 32
#define DD 300
#define QQ 200
#define VV 50000
#define NSLOT 55
#define MNEWS 2048           // BB*LL
#define MUSER 3200           // BB*HH
#define MTOT (NSLOT*MNEWS)   // 112640
#define SCAP 3200
#define NSL2 (NSLOT + 1)
#define JCMAX 256
#define MAXCH 25
#define CPAD 304

// wmma GEMM geometry (R15 known-good: 128x128 tile, single-buffered)
#define ALD 40               // A tile ld (bf16 elems), 128x32 + pad
#define BLD 136              // B tile ld, 32x128 + pad
#define CLD 136              // C smem ld (f32)
#define DSMB (128 * CLD * 4) // 69632 B

using namespace nvcuda;
typedef __nv_bfloat16 bf16;

__device__ __forceinline__ void split2(float x, bf16& h, bf16& l) {
    h = __float2bfloat16(x);
    l = __float2bfloat16(x - __bfloat162float(h));
}

// ---------------- static scratch ----------------
__device__ float d_embW[(size_t)VV * DD];
__device__ float d_vs[VV];
__device__ float d_vt[VV];
__device__ float d_V[(size_t)MTOT * DD];
__device__ float d_Wh[(size_t)MTOT * DD];
__device__ float d_sv[MTOT];
__device__ float d_tv[MTOT];
__device__ float d_enc[(size_t)NSLOT * BB * DD];
__device__ float d_uV[(size_t)MUSER * DD];
__device__ float d_uWh[(size_t)MUSER * DD];
__device__ float d_us[MUSER];
__device__ float d_ut[MUSER];
__device__ float d_uG[(size_t)MUSER * DD];
__device__ float d_user[(size_t)BB * DD];

__device__ float g_ts [(size_t)NSL2 * SCAP];
__device__ float g_E1 [(size_t)NSL2 * SCAP];
__device__ float g_E2 [(size_t)NSL2 * SCAP];
__device__ int   g_ti [(size_t)NSL2 * SCAP];
__device__ float g_thr[(size_t)NSL2 * SCAP];
__device__ float g_es1[(size_t)NSL2 * SCAP];
__device__ float g_es2[(size_t)NSL2 * SCAP];
__device__ int   g_si [(size_t)NSL2 * SCAP];

__device__ float g_cp1[(size_t)NSL2 * MAXCH * CPAD];
__device__ float g_cp2[(size_t)NSL2 * MAXCH * CPAD];
__device__ float g_cc1[NSL2 * MAXCH];
__device__ float g_cc2[NSL2 * MAXCH];

__device__ float g_score[MTOT];
__device__ float g_uscore[MUSER];
__device__ float g_lwTn[DD * QQ];
__device__ float g_lwTu[DD * QQ];

// ---------------- prep ----------------
__global__ void prep_kernel(const float* __restrict__ lwN, const float* __restrict__ lwU) {
    int i = blockIdx.x * 256 + threadIdx.x;
    if (i < MTOT) g_score[i] = 0.f;
    if (i < MUSER) { g_uscore[i] = 0.f; d_us[i] = 0.f; d_ut[i] = 0.f; }
    if (i < VV) { d_vs[i] = 0.f; d_vt[i] = 0.f; }
    if (i < DD * QQ) {
        int d = i / QQ, q = i - d * QQ;
        g_lwTn[i] = lwN[q * DD + d];
        g_lwTu[i] = lwU[q * DD + d];
    }
}

// ---------------- gather Wh rows (+ per-row s,t) ----------------
__global__ void gatherWh_kernel(const int* __restrict__ cand,
                                const int* __restrict__ clicked) {
    int row  = blockIdx.x * 8 + (threadIdx.x >> 5);
    int lane = threadIdx.x & 31;
    if (row >= MTOT) return;
    int slot = row / MNEWS;
    int r    = row - slot * MNEWS;
    int b = r >> 5, l = r & 31;
    int tok = (slot < CC) ? cand[(b * CC + slot) * LL + l]
                          : clicked[(b * HH + (slot - CC)) * LL + l];
    tok = min(max(tok, 0), VV - 1);
    const float2* src = (const float2*)(d_embW + (size_t)tok * DD);
    float2* dst = (float2*)(d_Wh + (size_t)row * DD);
    for (int c = lane; c < DD / 2; c += 32) dst[c] = src[c];
    if (!lane) { d_sv[row] = d_vs[tok]; d_tv[row] = d_vt[tok]; }
}

// ---------------- wmma split-bf16 GEMM core (R15): C tile left in smem --------
__device__ __forceinline__ void wgemm_compute(const float* __restrict__ A,
                                              const float* __restrict__ Bm,
                                              int NW, int M, int mBase, int nBase,
                                              char* smc) {
    bf16* Ahi = (bf16*)smc;
    bf16* Alo = Ahi + 128 * ALD;
    bf16* Bhi = Alo + 128 * ALD;
    bf16* Blo = Bhi + 32 * BLD;

    int tid = threadIdx.x;
    int wid = tid >> 5;
    int wm = wid & 3;
    int wn = wid >> 2;

    wmma::fragment<wmma::accumulator, 16, 16, 16, float> acc[2][4];
#pragma unroll
    for (int m = 0; m < 2; m++)
#pragma unroll
        for (int n = 0; n < 4; n++) wmma::fill_fragment(acc[m][n], 0.f);

    int arow = tid >> 3, acol = tid & 7;
    int bj = tid >> 3,  bc = (tid & 7) * 16;

    for (int kt = 0; kt < DD; kt += 32) {
#pragma unroll
        for (int rr = 0; rr < 4; rr++) {
            int row = arow + 32 * rr;
            float4 v = make_float4(0.f, 0.f, 0.f, 0.f);
            if ((mBase + row) < M && (kt + acol * 4 + 3) < DD)
                v = *(const float4*)&A[(size_t)(mBase + row) * DD + kt + acol * 4];
            bf16 h0, h1, h2, h3, l0, l1, l2, l3;
            split2(v.x, h0, l0); split2(v.y, h1, l1);
            split2(v.z, h2, l2); split2(v.w, h3, l3);
            __nv_bfloat162* ph = (__nv_bfloat162*)&Ahi[row * ALD + acol * 4];
            __nv_bfloat162* pl = (__nv_bfloat162*)&Alo[row * ALD + acol * 4];
            ph[0] = __halves2bfloat162(h0, h1); ph[1] = __halves2bfloat162(h2, h3);
            pl[0] = __halves2bfloat162(l0, l1); pl[1] = __halves2bfloat162(l2, l3);
        }
        {
            bool rok = (kt + bj) < DD;
#pragma unroll
            for (int q = 0; q < 4; q++) {
                int col = bc + q * 4;
                float4 v = make_float4(0.f, 0.f, 0.f, 0.f);
                if (rok && (nBase + col + 3) < NW)
                    v = *(const float4*)&Bm[(size_t)(kt + bj) * NW + nBase + col];
                bf16 h0, h1, h2, h3, l0, l1, l2, l3;
                split2(v.x, h0, l0); split2(v.y, h1, l1);
                split2(v.z, h2, l2); split2(v.w, h3, l3);
                __nv_bfloat162* ph = (__nv_bfloat162*)&Bhi[bj * BLD + col];
                __nv_bfloat162* pl = (__nv_bfloat162*)&Blo[bj * BLD + col];
                ph[0] = __halves2bfloat162(h0, h1); ph[1] = __halves2bfloat162(h2, h3);
                pl[0] = __halves2bfloat162(l0, l1); pl[1] = __halves2bfloat162(l2, l3);
            }
        }
        __syncthreads();
#pragma unroll
        for (int kk = 0; kk < 32; kk += 16) {
            wmma::fragment<wmma::matrix_a, 16, 16, 16, bf16, wmma::row_major> ah[2], al[2];
#pragma unroll
            for (int m = 0; m < 2; m++) {
                wmma::load_matrix_sync(ah[m], Ahi + (wm * 32 + m * 16) * ALD + kk, ALD);
                wmma::load_matrix_sync(al[m], Alo + (wm * 32 + m * 16) * ALD + kk, ALD);
            }
#pragma unroll
            for (int n = 0; n < 4; n++) {
                wmma::fragment<wmma::matrix_b, 16, 16, 16, bf16, wmma::row_major> bh, bl;
                wmma::load_matrix_sync(bh, Bhi + kk * BLD + wn * 64 + n * 16, BLD);
                wmma::load_matrix_sync(bl, Blo + kk * BLD + wn * 64 + n * 16, BLD);
#pragma unroll
                for (int m = 0; m < 2; m++) {
                    wmma::mma_sync(acc[m][n], ah[m], bh, acc[m][n]);
                    wmma::mma_sync(acc[m][n], ah[m], bl, acc[m][n]);
                    wmma::mma_sync(acc[m][n], al[m], bh, acc[m][n]);
                }
            }
        }
        __syncthreads();
    }

    float* Cs = (float*)smc;
#pragma unroll
    for (int m = 0; m < 2; m++)
#pragma unroll
        for (int n = 0; n < 4; n++)
            wmma::store_matrix_sync(Cs + (wm * 32 + m * 16) * CLD + wn * 64 + n * 16,
                                    acc[m][n], CLD, wmma::mem_row_major);
    __syncthreads();
}

// ---------------- SGEMM: C[M,300] = A[M,300] @ B[300,300] + fused s,t ----------
__global__ void __launch_bounds__(256, 2)
gemm_kernel(const float* __restrict__ A, const float* __restrict__ Bm,
            float* __restrict__ Cm, int M,
            const float* __restrict__ a2, float* __restrict__ sv, float* __restrict__ tv) {
    extern __shared__ __align__(16) char smc[];
    int nBase = blockIdx.x * 128;
    int mBase = blockIdx.y * 128;
    int tid = threadIdx.x;
    int ti = tid >> 4, td = tid & 15;

    wgemm_compute(A, Bm, DD, M, mBase, nBase, smc);
    const float* Cs = (const float*)smc;

    int col0 = nBase + td * 8;
#pragma unroll
    for (int r = 0; r < 8; r++) {
        int mrow = mBase + ti * 8 + r;
        if (mrow >= M) continue;
        float* crow = Cm + (size_t)mrow * DD;
        float o[8];
#pragma unroll
        for (int e = 0; e < 8; e++) o[e] = Cs[(ti * 8 + r) * CLD + td * 8 + e];
        if (col0 + 7 < DD) {
            *(float4*)&crow[col0]     = make_float4(o[0], o[1], o[2], o[3]);
            *(float4*)&crow[col0 + 4] = make_float4(o[4], o[5], o[6], o[7]);
        } else {
#pragma unroll
            for (int e = 0; e < 8; e++)
                if (col0 + e < DD) crow[col0 + e] = o[e];
        }
        float sp = 0.f, tp = 0.f;
#pragma unroll
        for (int e = 0; e < 8; e++) {
            int col = col0 + e;
            if (col < DD) {
                sp += o[e] * a2[col];
                tp += o[e] * a2[DD + col];
            }
        }
        atomicAdd(&sv[mrow], sp);
        atomicAdd(&tv[mrow], tp);
    }
}

// ---------------- score GEMM ----------------
__global__ void __launch_bounds__(256, 2)
score_gemm_kernel(const float* __restrict__ A, const float* __restrict__ Bt,
                  const float* __restrict__ lin_b, const float* __restrict__ query,
                  float* __restrict__ score) {
    extern __shared__ __align__(16) char smc[];
    __shared__ float ssum[128];
    int nBase = blockIdx.x * 128;
    int mBase = blockIdx.y * 128;
    int tid = threadIdx.x;
    int ti = tid >> 4, td = tid & 15;

    wgemm_compute(A, Bt, QQ, 0x7fffffff, mBase, nBase, smc);
    const float* Cs = (const float*)smc;

    if (tid < 128) ssum[tid] = 0.f;
    __syncthreads();

    int col0 = nBase + td * 8;
#pragma unroll
    for (int r = 0; r < 8; r++) {
        float rs = 0.f;
#pragma unroll
        for (int e = 0; e < 8; e++) {
            int col = col0 + e;
            if (col < QQ) {
                float o = Cs[(ti * 8 + r) * CLD + td * 8 + e];
                rs += tanhf(o + lin_b[col]) * query[col];
            }
        }
        atomicAdd(&ssum[ti * 8 + r], rs);
    }
    __syncthreads();
    if (tid < 128) atomicAdd(&score[mBase + tid], ssum[tid]);
}

// ---------------- bitonic sort (two independent phases via blockIdx.y) ---------
template<int NS>
__device__ void bitonicNS(float* key, int* val) {
    for (int k = 2; k <= NS; k <<= 1) {
        for (int j = k >> 1; j > 0; j >>= 1) {
            for (int t = threadIdx.x; t < NS / 2; t += blockDim.x) {
                int i = 2 * t - (t & (j - 1));
                int l = i + j;
                bool up = ((i & k) == 0);
                float ki = key[i], kl = key[l];
                if (up ? (ki > kl) : (ki < kl)) {
                    key[i] = kl; key[l] = ki;
                    int vi = val[i]; val[i] = val[l]; val[l] = vi;
                }
            }
            __syncthreads();
        }
    }
}

template<int NS>
__global__ void __launch_bounds__(1024)
sort_kernel(const float* __restrict__ tv, const float* __restrict__ sv,
            int M, int slotBase) {
    __shared__ float key[NS];
    __shared__ int   val[NS];
    int slot = slotBase + blockIdx.x;
    size_t sb = (size_t)slot * SCAP;

    if (blockIdx.y == 0) {
        const float* t = tv + (size_t)blockIdx.x * M;
        for (int i = threadIdx.x; i < NS; i += blockDim.x) {
            key[i] = (i < M) ? t[i] : 3.0e38f;
            val[i] = i;
        }
        __syncthreads();
        bitonicNS<NS>(key, val);
        for (int i = threadIdx.x; i < M; i += blockDim.x) {
            float k = key[i];
            g_ts[sb + i] = k;
            g_ti[sb + i] = val[i];
            g_E1[sb + i] = __expf(k);
            g_E2[sb + i] = __expf(0.2f * k);
        }
    } else {
        const float* s = sv + (size_t)blockIdx.x * M;
        for (int i = threadIdx.x; i < NS; i += blockDim.x) {
            key[i] = (i < M) ? (-s[i]) : 3.0e38f;
            val[i] = i;
        }
        __syncthreads();
        bitonicNS<NS>(key, val);
        for (int i = threadIdx.x; i < M; i += blockDim.x) {
            float k = key[i];
            g_thr[sb + i] = k;
            g_si [sb + i] = val[i];
            g_es1[sb + i] = __expf(-k);
            g_es2[sb + i] = __expf(-0.2f * k);
        }
    }
}

// ---------------- phase A: per-chunk partial sums (chunk size jc) --------------
__global__ void __launch_bounds__(320)
partials_kernel(const float* __restrict__ Wbase, size_t wStride, int M, int slotBase, int jc) {
    int slot = slotBase + blockIdx.y;
    size_t sb = (size_t)slot * SCAP;
    const float* W = Wbase + (size_t)blockIdx.y * wStride;
    int ch = blockIdx.x;
    int jstart = ch * jc, jend = min(M, jstart + jc);
    int t = threadIdx.x;

    if (t < DD) {
        int d = t;
        float p1 = 0.f, p2 = 0.f;
        float wb[4];
#pragma unroll
        for (int q = 0; q < 4; q++) wb[q] = W[(size_t)g_ti[sb + jstart + q] * DD + d];
        for (int jb = jstart; jb < jend; jb += 4) {
            float wn[4] = {0.f, 0.f, 0.f, 0.f};
            if (jb + 4 < jend) {
#pragma unroll
                for (int q = 0; q < 4; q++)
                    wn[q] = W[(size_t)g_ti[sb + jb + 4 + q] * DD + d];
            }
#pragma unroll
            for (int q = 0; q < 4; q++) {
                float e1 = g_E1[sb + jb + q], e2 = g_E2[sb + jb + q];
                p1 += e1 * wb[q]; p2 += e2 * wb[q];
            }
#pragma unroll
            for (int q = 0; q < 4; q++) wb[q] = wn[q];
        }
        size_t o = (size_t)(slot * MAXCH + ch) * CPAD + d;
        g_cp1[o] = p1; g_cp2[o] = p2;
    } else if (t == DD) {
        float c = 0.f;
        for (int j = jstart; j < jend; j++) c += g_E1[sb + j];
        g_cc1[slot * MAXCH + ch] = c;
    } else if (t == DD + 1) {
        float c = 0.f;
        for (int j = jstart; j < jend; j++) c += g_E2[sb + j];
        g_cc2[slot * MAXCH + ch] = c;
    }
}

// ---------------- phase C: per-chunk merge sweep (chunk size jc) ---------------
__global__ void __launch_bounds__(320)
csweep_kernel(const float* __restrict__ Wbase, size_t wStride, float* __restrict__ G_all,
              int M, int slotBase, int nch, int jc) {
    __shared__ float ts[JCMAX], e1s[JCMAX], e2s[JCMAX];
    __shared__ int tis[JCMAX];
    int slot = slotBase + blockIdx.y;
    size_t sb = (size_t)slot * SCAP;
    const float* W = Wbase + (size_t)blockIdx.y * wStride;
    float* G = G_all + (size_t)blockIdx.y * M * DD;
    int ch = blockIdx.x;
    int jstart = ch * jc, jend = min(M, jstart + jc);
    int jn = jend - jstart;

    for (int i = threadIdx.x; i < jn; i += blockDim.x) {
        ts[i]  = g_ts[sb + jstart + i];
        e1s[i] = g_E1[sb + jstart + i];
        e2s[i] = g_E2[sb + jstart + i];
        tis[i] = g_ti[sb + jstart + i];
    }
    __syncthreads();

    int t = threadIdx.x;
    bool act = t < DD;
    int d = act ? t : DD - 1;

    float p1 = 0.f, p2 = 0.f, c1 = 0.f, c2 = 0.f, T1 = 0.f, C1 = 0.f;
    int base = slot * MAXCH;
    for (int k = 0; k < nch; k++) {
        float v1 = g_cp1[(size_t)(base + k) * CPAD + d];
        float s1 = g_cc1[base + k];
        T1 += v1; C1 += s1;
        if (k < ch) {
            p1 += v1; c1 += s1;
            p2 += g_cp2[(size_t)(base + k) * CPAD + d];
            c2 += g_cc2[base + k];
        }
    }

    float tPrev = (jstart == 0) ? -3.4e38f : g_ts[sb + jstart - 1];
    int lo = 0, hi = M;
    while (lo < hi) { int mid = (lo + hi) >> 1; if (g_thr[sb + mid] <= tPrev) lo = mid + 1; else hi = mid; }
    int ptr = lo;
    int r1 = M;
    if (jend < M) {
        float tLast = ts[jn - 1];
        lo = 0; hi = M;
        while (lo < hi) { int mid = (lo + hi) >> 1; if (g_thr[sb + mid] <= tLast) lo = mid + 1; else hi = mid; }
        r1 = lo;
    }

    float wb[4];
#pragma unroll
    for (int q = 0; q < 4; q++) wb[q] = W[(size_t)tis[q] * DD + d];

    for (int jb = 0; jb < jn; jb += 4) {
        float wn[4] = {0.f, 0.f, 0.f, 0.f};
        if (jb + 4 < jn) {
#pragma unroll
            for (int q = 0; q < 4; q++) wn[q] = W[(size_t)tis[jb + 4 + q] * DD + d];
        }
#pragma unroll
        for (int q = 0; q < 4; q++) {
            float tj = ts[jb + q];
            while (ptr < r1 && g_thr[sb + ptr] <= tj) {
                float a1 = g_es1[sb + ptr], a2 = g_es2[sb + ptr];
                int si = g_si[sb + ptr];
                float den = a1 * (C1 - c1) + a2 * c2;
                float v = __fdividef(a1 * (T1 - p1) + a2 * p2, den);
                v = (v > 0.f) ? v : (__expf(v) - 1.f);
                if (act) G[(size_t)si * DD + d] = v;
                ptr++;
            }
            float e1 = e1s[jb + q], e2 = e2s[jb + q];
            p1 += e1 * wb[q]; p2 += e2 * wb[q];
            c1 += e1; c2 += e2;
        }
#pragma unroll
        for (int q = 0; q < 4; q++) wb[q] = wn[q];
    }
    while (ptr < r1) {
        float a1 = g_es1[sb + ptr], a2 = g_es2[sb + ptr];
        int si = g_si[sb + ptr];
        float den = a1 * (C1 - c1) + a2 * c2;
        float v = __fdividef(a1 * (T1 - p1) + a2 * p2, den);
        v = (v > 0.f) ? v : (__expf(v) - 1.f);
        if (act) G[(size_t)si * DD + d] = v;
        ptr++;
    }
}

// ---------------- softmax + weighted sum ----------------
__global__ void softsum_kernel(const float* __restrict__ X, const float* __restrict__ sc,
                               int S, int slotM, float* __restrict__ outB) {
    __shared__ float wsm[64];
    int b = blockIdx.x, slot = blockIdx.y;
    int rowBase = slot * slotM + b * S;
    int lane = threadIdx.x;
    if (threadIdx.x < 32) {
        float v0 = (lane < S) ? sc[rowBase + lane] : -1e30f;
        float v1 = ((lane + 32) < S) ? sc[rowBase + lane + 32] : -1e30f;
        float m = fmaxf(v0, v1);
#pragma unroll
        for (int o = 16; o; o >>= 1) m = fmaxf(m, __shfl_xor_sync(0xffffffffu, m, o));
        float e0 = (lane < S) ? __expf(v0 - m) : 0.f;
        float e1 = ((lane + 32) < S) ? __expf(v1 - m) : 0.f;
        float sum = e0 + e1;
#pragma unroll
        for (int o = 16; o; o >>= 1) sum += __shfl_xor_sync(0xffffffffu, sum, o);
        float inv = 1.f / sum;
        wsm[lane] = e0 * inv;
        wsm[lane + 32] = e1 * inv;
    }
    __syncthreads();
    float* o = outB + (size_t)(slot * BB + b) * DD;
    for (int dd = threadIdx.x; dd < DD; dd += blockDim.x) {
        float acc = 0.f;
        for (int s = 0; s < S; s++)
            acc += wsm[s] * X[(size_t)(rowBase + s) * DD + dd];
        o[dd] = acc;
    }
}

// ---------------- reorder clicked encodings ----------------
__global__ void copy_uV_kernel() {
    int row  = blockIdx.x * 8 + (threadIdx.x >> 5);
    int lane = threadIdx.x & 31;
    if (row >= MUSER) return;
    int b = row / HH, j = row - b * HH;
    const float* src = d_enc + ((size_t)(CC + j) * BB + b) * DD;
    float* dst = d_uV + (size_t)row * DD;
    for (int c = lane; c < DD; c += 32) dst[c] = src[c];
}

// ---------------- final scores ----------------
__global__ void scores_kernel(float* __restrict__ out) {
    int w    = (blockIdx.x * blockDim.x + threadIdx.x) >> 5;
    int lane = threadIdx.x & 31;
    if (w >= BB * CC) return;
    int b = w / CC, c = w - b * CC;
    const float* cd = d_enc + ((size_t)c * BB + b) * DD;
    const float* u  = d_user + (size_t)b * DD;
    float acc = 0.f;
    for (int k = lane; k < DD; k += 32) acc += cd[k] * u[k];
#pragma unroll
    for (int o = 16; o; o >>= 1) acc += __shfl_xor_sync(0xffffffffu, acc, o);
    if (!lane) out[b * CC + c] = acc;
}

// ---------------- launch ----------------
extern "C" void kernel_launch(void* const* d_in, const int* in_sizes, int n_in,
                              void* d_out, int out_size) {
    const void* by200[4] = {0, 0, 0, 0};
    const void* by600[2] = {0, 0};
    const void* by60k[2] = {0, 0};
    const void* by90k[2] = {0, 0};
    const int* cand = 0; const int* clicked = 0; const float* emb = 0;
    int n200 = 0, n600 = 0, n60k = 0, n90k = 0;
    for (int i = 0; i < n_in; i++) {
        int sz = in_sizes[i];
        if      (sz == BB * CC * LL)      cand    = (const int*)d_in[i];
        else if (sz == BB * HH * LL)      clicked = (const int*)d_in[i];
        else if (sz == VV * DD)           emb     = (const float*)d_in[i];
        else if (sz == DD * DD  && n90k < 2) by90k[n90k++] = d_in[i];
        else if (sz == 2 * DD   && n600 < 2) by600[n600++] = d_in[i];
        else if (sz == QQ * DD  && n60k < 2) by60k[n60k++] = d_in[i];
        else if (sz == QQ       && n200 < 4) by200[n200++] = d_in[i];
    }
    const float* news_W     = (const float*)by90k[0];
    const float* user_W     = (const float*)by90k[1];
    const float* news_a     = (const float*)by600[0];
    const float* user_a     = (const float*)by600[1];
    const float* news_lin_w = (const float*)by60k[0];
    const float* user_lin_w = (const float*)by60k[1];
    const float* news_lin_b = (const float*)by200[0];
    const float* news_query = (const float*)by200[1];
    const float* user_lin_b = (const float*)by200[2];
    const float* user_query = (const float*)by200[3];
    float* out = (float*)d_out;

    float *pEmbW, *pVs, *pVt, *pV, *pWh, *pS, *pT, *pEnc;
    float *pUV, *pUWh, *pUS, *pUT, *pUG, *pUser;
    float *pScore, *pUScore, *pLwTn, *pLwTu;
    cudaGetSymbolAddress((void**)&pEmbW, d_embW);
    cudaGetSymbolAddress((void**)&pVs, d_vs);
    cudaGetSymbolAddress((void**)&pVt, d_vt);
    cudaGetSymbolAddress((void**)&pV, d_V);
    cudaGetSymbolAddress((void**)&pWh, d_Wh);
    cudaGetSymbolAddress((void**)&pS, d_sv);
    cudaGetSymbolAddress((void**)&pT, d_tv);
    cudaGetSymbolAddress((void**)&pEnc, d_enc);
    cudaGetSymbolAddress((void**)&pUV, d_uV);
    cudaGetSymbolAddress((void**)&pUWh, d_uWh);
    cudaGetSymbolAddress((void**)&pUS, d_us);
    cudaGetSymbolAddress((void**)&pUT, d_ut);
    cudaGetSymbolAddress((void**)&pUG, d_uG);
    cudaGetSymbolAddress((void**)&pUser, d_user);
    cudaGetSymbolAddress((void**)&pScore, g_score);
    cudaGetSymbolAddress((void**)&pUScore, g_uscore);
    cudaGetSymbolAddress((void**)&pLwTn, g_lwTn);
    cudaGetSymbolAddress((void**)&pLwTu, g_lwTu);

    const int JC_NEWS = 256;
    const int JC_USER = 128;
    const int NCH_NEWS = (MNEWS + JC_NEWS - 1) / JC_NEWS;   // 8
    const int NCH_USER = (MUSER + JC_USER - 1) / JC_USER;   // 25

    cudaFuncSetAttribute(gemm_kernel, cudaFuncAttributeMaxDynamicSharedMemorySize, DSMB);
    cudaFuncSetAttribute(score_gemm_kernel, cudaFuncAttributeMaxDynamicSharedMemorySize, DSMB);

    // prep (zeros + both lin_w transposes)
    prep_kernel<<<(MTOT + 255) / 256, 256>>>(news_lin_w, user_lin_w);

    // news pipeline
    gemm_kernel<<<dim3(3, (VV + 127) / 128), 256, DSMB>>>(emb, news_W, pEmbW, VV,
                                                          news_a, pVs, pVt);
    gatherWh_kernel<<<MTOT / 8, 256>>>(cand, clicked);
    sort_kernel<2048><<<dim3(NSLOT, 2), 1024>>>(pT, pS, MNEWS, 0);
    partials_kernel<<<dim3(NCH_NEWS, NSLOT), 320>>>(pWh, (size_t)MNEWS * DD, MNEWS, 0, JC_NEWS);
    csweep_kernel<<<dim3(NCH_NEWS, NSLOT), 320>>>(pWh, (size_t)MNEWS * DD, pV, MNEWS, 0, NCH_NEWS, JC_NEWS);
    score_gemm_kernel<<<dim3(2, MTOT / 128), 256, DSMB>>>(pV, pLwTn, news_lin_b, news_query, pScore);
    softsum_kernel<<<dim3(BB, NSLOT), 128>>>(pV, pScore, LL, MNEWS, pEnc);

    // user pipeline
    copy_uV_kernel<<<MUSER / 8, 256>>>();
    gemm_kernel<<<dim3(3, MUSER / 128), 256, DSMB>>>(pUV, user_W, pUWh, MUSER,
                                                     user_a, pUS, pUT);
    sort_kernel<4096><<<dim3(1, 2), 1024>>>(pUT, pUS, MUSER, NSLOT);
    partials_kernel<<<dim3(NCH_USER, 1), 320>>>(pUWh, 0, MUSER, NSLOT, JC_USER);
    csweep_kernel<<<dim3(NCH_USER, 1), 320>>>(pUWh, 0, pUG, MUSER, NSLOT, NCH_USER, JC_USER);
    score_gemm_kernel<<<dim3(2, MUSER / 128), 256, DSMB>>>(pUG, pLwTu, user_lin_b, user_query, pUScore);
    softsum_kernel<<<dim3(BB, 1), 128>>>(pUG, pUScore, HH, MUSER, pUser);

    scores_kernel<<<40, 256>>>(out);
}